// round 7
// baseline (speedup 1.0000x reference)
#include <cuda_runtime.h>
#include <math.h>

#define K 32
#define G 256
#define XMIN -6.5f
#define RANGE 13.0f
#define INV_H (G / RANGE)
#define H_STEP (RANGE / G)
#define INV_SQRT_2PI 0.3989422804014327f
#define S_CONST 0.8493218002880191f  // sqrt(0.5*log2(e))
#define EPS 2.2204460492503131e-16f
#define NCHUNK 9                     // ceil((G-1)/31)
#define NBLOCKS 148

__device__ float2 g_tabF[G * K];
__device__ float2 g_tabI[G * K];

__device__ __forceinline__ float ex2f(float x) {
    float r;
    asm("ex2.approx.ftz.f32 %0, %1;" : "=f"(r) : "f"(x));
    return r;
}

// ---------------- fused prep + build ----------------
__global__ void __launch_bounds__(512) build_kernel(const float* __restrict__ Wk0,
                                                    const float* __restrict__ W10,
                                                    const float* __restrict__ W21,
                                                    const float* __restrict__ mu,
                                                    const float* __restrict__ sigma) {
    __shared__ float4 s_tab[K * K];
    __shared__ float w0s[K];

    int lane = threadIdx.x & 31;
    int w = threadIdx.x >> 5;

    if (w == 0) {
        float v = Wk0[lane];
        float mx = v;
#pragma unroll
        for (int o = 16; o; o >>= 1) mx = fmaxf(mx, __shfl_xor_sync(~0u, mx, o));
        float e = __expf(v - mx);
        float s = e;
#pragma unroll
        for (int o = 16; o; o >>= 1) s += __shfl_xor_sync(~0u, s, o);
        w0s[lane] = e / s;
    }

    float w10v[2], w21v[2], sgv[2], muv[2];
#pragma unroll
    for (int c = 0; c < 2; c++) {
        int j = w + c * 16;
        int idx = lane * K + j;
        float v10 = W10[idx];
        float v21 = W21[idx];
        sgv[c] = sigma[idx];
        muv[c] = mu[idx];
        float mx10 = v10, mx21 = v21;
#pragma unroll
        for (int o = 16; o; o >>= 1) {
            mx10 = fmaxf(mx10, __shfl_xor_sync(~0u, mx10, o));
            mx21 = fmaxf(mx21, __shfl_xor_sync(~0u, mx21, o));
        }
        float e10 = __expf(v10 - mx10);
        float e21 = __expf(v21 - mx21);
        float s10 = e10, s21 = e21;
#pragma unroll
        for (int o = 16; o; o >>= 1) {
            s10 += __shfl_xor_sync(~0u, s10, o);
            s21 += __shfl_xor_sync(~0u, s21, o);
        }
        w10v[c] = e10 / s10;
        w21v[c] = e21 / s21;
    }
    __syncthreads();

#pragma unroll
    for (int c = 0; c < 2; c++) {
        int j = w + c * 16;
        float inv_sg = 1.f / sgv[c];
        float4 t;
        t.x = S_CONST * inv_sg;
        t.y = -S_CONST * muv[c] * inv_sg;
        t.z = w21v[c] * INV_SQRT_2PI * inv_sg;
        t.w = w10v[c] * w0s[j] * INV_SQRT_2PI * inv_sg;
        s_tab[lane * K + j] = t;
    }
    __syncthreads();

    int chunk = blockIdx.x;
    int tsel = blockIdx.y;
    int g = chunk * 31 + lane;
    if (g > G - 1) g = G - 1;
    float x = XMIN + g * H_STEP;

#pragma unroll
    for (int c = 0; c < 2; c++) {
        int f = w + c * 16;
        float v = 0.f;
        if (tsel == 0) {
#pragma unroll
            for (int j = 0; j < K; j++) {
                float4 t = s_tab[f * K + j];
                float u = fmaf(x, t.x, t.y);
                v = fmaf(t.w, ex2f(-u * u), v);
            }
        } else {
#pragma unroll
            for (int i = 0; i < K; i++) {
                float4 t = s_tab[i * K + f];
                float u = fmaf(x, t.x, t.y);
                v = fmaf(t.z, ex2f(-u * u), v);
            }
        }
        float vn = __shfl_down_sync(0xffffffffu, v, 1);
        if (lane < 31 && g < G - 1) {
            float2 e;
            e.x = v;
            e.y = vn - v;
            if (tsel == 0) g_tabF[g * K + f] = e;
            else           g_tabI[g * K + f] = e;
        }
    }
}

// ---------------- main: tables in smem, warp-cooperative, shfl reduction ----------------
// Dynamic smem: sF[G*16] float4 (64KB) then sI[G*16] float4 (64KB).
__global__ void __launch_bounds__(1024) tt_main(const float* __restrict__ X,
                                                float* __restrict__ out, int n) {
    extern __shared__ float4 dyn[];
    float4* sF = dyn;             // [G*16]  row g: 16 float4 = comps (2p,2p+1)
    float4* sI = dyn + G * 16;

    __shared__ float4 sp[32][32];  // [warp][sample-in-tile]
    __shared__ float res[32][32];

    int tid = threadIdx.x;
    int lane = tid & 31;
    int w = tid >> 5;

    // stage both tables: 8192 float4 total, 1024 threads -> 8 each
    const float4* gF = (const float4*)g_tabF;
    const float4* gI = (const float4*)g_tabI;
#pragma unroll
    for (int i = 0; i < 4; i++) sF[tid + i * 1024] = gF[tid + i * 1024];
#pragma unroll
    for (int i = 0; i < 4; i++) sI[tid + i * 1024] = gI[tid + i * 1024];
    __syncthreads();

    // per-block contiguous sample chunk
    int chunk = (n + NBLOCKS - 1) / NBLOCKS;
    int cs = blockIdx.x * chunk;
    int ce = min(cs + chunk, n);

    int half = lane >> 4;   // 0: even sample of pair, 1: odd
    int pair = lane & 15;   // component pair index

    for (int s0 = cs + w * 32; s0 < ce; s0 += 32 * 32) {
        int sidx = s0 + lane;
        float2 x = make_float2(0.f, 0.f);
        if (sidx < n) x = ((const float2*)X)[sidx];

        float t0 = (x.x - XMIN) * INV_H;
        float t1 = (x.y - XMIN) * INV_H;
        float g0f = fminf(fmaxf(floorf(t0), 0.f), (float)(G - 2));
        float g1f = fminf(fmaxf(floorf(t1), 0.f), (float)(G - 2));
        sp[w][lane] = make_float4(g0f, t0 - g0f, g1f, t1 - g1f);
        __syncwarp();

#pragma unroll
        for (int t = 0; t < 16; t++) {
            float4 p = sp[w][2 * t + half];
            float4 fF = sF[((int)p.x) * 16 + pair];
            float4 fI = sI[((int)p.z) * 16 + pair];
            float vF0 = fmaf(p.y, fF.y, fF.x);
            float vF1 = fmaf(p.y, fF.w, fF.z);
            float vI0 = fmaf(p.w, fI.y, fI.x);
            float vI1 = fmaf(p.w, fI.w, fI.z);
            float s = vF0 * vI0 + vF1 * vI1;
            // reduce over 16 pairs within each half
            s += __shfl_xor_sync(~0u, s, 1);
            s += __shfl_xor_sync(~0u, s, 2);
            s += __shfl_xor_sync(~0u, s, 4);
            s += __shfl_xor_sync(~0u, s, 8);
            if (pair == 0) res[w][2 * t + half] = s;
        }
        __syncwarp();

        if (sidx < ce) out[sidx] = __logf(res[w][lane] + EPS);
        __syncwarp();
    }
}

extern "C" void kernel_launch(void* const* d_in, const int* in_sizes, int n_in,
                              void* d_out, int out_size) {
    const float* X     = (const float*)d_in[0];
    const float* Wk0   = (const float*)d_in[1];
    const float* Wk1k0 = (const float*)d_in[2];
    const float* Wk2k1 = (const float*)d_in[3];
    const float* mu    = (const float*)d_in[4];
    const float* sigma = (const float*)d_in[5];
    float* out = (float*)d_out;
    int n = in_sizes[0] / 2;

    static int smem_set = 0;
    int dyn_bytes = 2 * G * 16 * sizeof(float4);  // 131072
    if (!smem_set) {
        cudaFuncSetAttribute(tt_main, cudaFuncAttributeMaxDynamicSharedMemorySize, dyn_bytes);
        smem_set = 1;
    }

    build_kernel<<<dim3(NCHUNK, 2), 512>>>(Wk0, Wk1k0, Wk2k1, mu, sigma);
    tt_main<<<NBLOCKS, 1024, dyn_bytes>>>(X, out, n);
}

// round 8
// speedup vs baseline: 1.0152x; 1.0152x over previous
#include <cuda_runtime.h>
#include <math.h>

#define K 32
#define G 256
#define XMIN -6.5f
#define RANGE 13.0f
#define INV_H (G / RANGE)
#define H_STEP (RANGE / G)
#define INV_SQRT_2PI 0.3989422804014327f
#define S_CONST 0.8493218002880191f  // sqrt(0.5*log2(e))
#define EPS 2.2204460492503131e-16f

__device__ float g_tabFv[G * K];  // F_a(x_g) values, row g = 32 floats
__device__ float g_tabIv[G * K];  // I_a(x_g) values

__device__ __forceinline__ float ex2f(float x) {
    float r;
    asm("ex2.approx.ftz.f32 %0, %1;" : "=f"(r) : "f"(x));
    return r;
}

// ---------------- fused prep + build (values only) ----------------
// grid dim3(8, 2), 512 threads. Each block folds the softmax coefficient table
// into smem, then computes a 32-point slice (g = bx*32 + lane) of all 32
// functions of one table (blockIdx.y: 0=F, 1=I). Warp w owns f = {w, w+16}.
__global__ void __launch_bounds__(512) build_kernel(const float* __restrict__ Wk0,
                                                    const float* __restrict__ W10,
                                                    const float* __restrict__ W21,
                                                    const float* __restrict__ mu,
                                                    const float* __restrict__ sigma) {
    __shared__ float4 s_tab[K * K];
    __shared__ float w0s[K];

    int lane = threadIdx.x & 31;
    int w = threadIdx.x >> 5;

    if (w == 0) {
        float v = Wk0[lane];
        float mx = v;
#pragma unroll
        for (int o = 16; o; o >>= 1) mx = fmaxf(mx, __shfl_xor_sync(~0u, mx, o));
        float e = __expf(v - mx);
        float s = e;
#pragma unroll
        for (int o = 16; o; o >>= 1) s += __shfl_xor_sync(~0u, s, o);
        w0s[lane] = e / s;
    }

    float w10v[2], w21v[2], sgv[2], muv[2];
#pragma unroll
    for (int c = 0; c < 2; c++) {
        int j = w + c * 16;
        int idx = lane * K + j;
        float v10 = W10[idx];
        float v21 = W21[idx];
        sgv[c] = sigma[idx];
        muv[c] = mu[idx];
        float mx10 = v10, mx21 = v21;
#pragma unroll
        for (int o = 16; o; o >>= 1) {
            mx10 = fmaxf(mx10, __shfl_xor_sync(~0u, mx10, o));
            mx21 = fmaxf(mx21, __shfl_xor_sync(~0u, mx21, o));
        }
        float e10 = __expf(v10 - mx10);
        float e21 = __expf(v21 - mx21);
        float s10 = e10, s21 = e21;
#pragma unroll
        for (int o = 16; o; o >>= 1) {
            s10 += __shfl_xor_sync(~0u, s10, o);
            s21 += __shfl_xor_sync(~0u, s21, o);
        }
        w10v[c] = e10 / s10;
        w21v[c] = e21 / s21;
    }
    __syncthreads();

#pragma unroll
    for (int c = 0; c < 2; c++) {
        int j = w + c * 16;
        float inv_sg = 1.f / sgv[c];
        float4 t;
        t.x = S_CONST * inv_sg;
        t.y = -S_CONST * muv[c] * inv_sg;
        t.z = w21v[c] * INV_SQRT_2PI * inv_sg;
        t.w = w10v[c] * w0s[j] * INV_SQRT_2PI * inv_sg;
        s_tab[lane * K + j] = t;
    }
    __syncthreads();

    int g = blockIdx.x * 32 + lane;
    int tsel = blockIdx.y;
    float x = XMIN + g * H_STEP;

#pragma unroll
    for (int c = 0; c < 2; c++) {
        int f = w + c * 16;
        float v = 0.f;
        if (tsel == 0) {
#pragma unroll
            for (int j = 0; j < K; j++) {
                float4 t = s_tab[f * K + j];
                float u = fmaf(x, t.x, t.y);
                v = fmaf(t.w, ex2f(-u * u), v);
            }
            g_tabFv[g * K + f] = v;
        } else {
#pragma unroll
            for (int i = 0; i < K; i++) {
                float4 t = s_tab[i * K + f];
                float u = fmaf(x, t.x, t.y);
                v = fmaf(t.z, ex2f(-u * u), v);
            }
            g_tabIv[g * K + f] = v;
        }
    }
}

// ---------------- main: value tables in 64KB smem, 2 CTAs/SM ----------------
__global__ void __launch_bounds__(512, 2) tt_main(const float* __restrict__ X,
                                                  float* __restrict__ out, int n) {
    extern __shared__ float dyn[];
    float* sFv = dyn;            // [G*32]
    float* sIv = dyn + G * K;    // [G*32]

    __shared__ float4 sp[16][32];
    __shared__ float prodm[16][32][17];

    int tid = threadIdx.x;
    int lane = tid & 31;
    int w = tid >> 5;

    // stage both value tables: 2 * 2048 float4, 512 threads -> 8 float4 each
    {
        float4* dF = (float4*)sFv;
        float4* dI = (float4*)sIv;
        const float4* gF = (const float4*)g_tabFv;
        const float4* gI = (const float4*)g_tabIv;
#pragma unroll
        for (int i = 0; i < 4; i++) dF[tid + i * 512] = gF[tid + i * 512];
#pragma unroll
        for (int i = 0; i < 4; i++) dI[tid + i * 512] = gI[tid + i * 512];
    }
    __syncthreads();

    int gwid = blockIdx.x * 16 + w;        // global warp-task id
    int sbase = gwid * 32;
    if (sbase >= n) return;

    int sidx = sbase + lane;
    float2 x = make_float2(0.f, 0.f);
    if (sidx < n) x = ((const float2*)X)[sidx];

    float t0 = (x.x - XMIN) * INV_H;
    float t1 = (x.y - XMIN) * INV_H;
    float g0f = fminf(fmaxf(floorf(t0), 0.f), (float)(G - 2));
    float g1f = fminf(fmaxf(floorf(t1), 0.f), (float)(G - 2));
    sp[w][lane] = make_float4(g0f, t0 - g0f, g1f, t1 - g1f);
    __syncwarp();

    int half = lane >> 4;   // lanes 0-15: even sample of pair; 16-31: odd
    int pair = lane & 15;   // component pair (comps 2p, 2p+1)

#pragma unroll
    for (int t = 0; t < 16; t++) {
        float4 p = sp[w][2 * t + half];
        int ga = (int)p.x;
        int gb = (int)p.z;
        float2 vF0 = *(const float2*)&sFv[ga * K + 2 * pair];
        float2 vF1 = *(const float2*)&sFv[(ga + 1) * K + 2 * pair];
        float2 vI0 = *(const float2*)&sIv[gb * K + 2 * pair];
        float2 vI1 = *(const float2*)&sIv[(gb + 1) * K + 2 * pair];
        float a0 = fmaf(p.y, vF1.x - vF0.x, vF0.x);
        float a1 = fmaf(p.y, vF1.y - vF0.y, vF0.y);
        float b0 = fmaf(p.w, vI1.x - vI0.x, vI0.x);
        float b1 = fmaf(p.w, vI1.y - vI0.y, vI0.y);
        prodm[w][2 * t + half][pair] = a0 * b0 + a1 * b1;
    }
    __syncwarp();

    float acc = 0.f;
#pragma unroll
    for (int i = 0; i < 16; i++) acc += prodm[w][lane][i];

    if (sidx < n) out[sidx] = __logf(acc + EPS);
}

extern "C" void kernel_launch(void* const* d_in, const int* in_sizes, int n_in,
                              void* d_out, int out_size) {
    const float* X     = (const float*)d_in[0];
    const float* Wk0   = (const float*)d_in[1];
    const float* Wk1k0 = (const float*)d_in[2];
    const float* Wk2k1 = (const float*)d_in[3];
    const float* mu    = (const float*)d_in[4];
    const float* sigma = (const float*)d_in[5];
    float* out = (float*)d_out;
    int n = in_sizes[0] / 2;

    static int smem_set = 0;
    int dyn_bytes = 2 * G * K * sizeof(float);  // 65536
    if (!smem_set) {
        cudaFuncSetAttribute(tt_main, cudaFuncAttributeMaxDynamicSharedMemorySize, dyn_bytes);
        smem_set = 1;
    }

    build_kernel<<<dim3(8, 2), 512>>>(Wk0, Wk1k0, Wk2k1, mu, sigma);
    int ntasks = (n + 31) / 32;             // 32-sample warp tasks
    int blocks = (ntasks + 15) / 16;        // 16 warps per block
    tt_main<<<blocks, 512, dyn_bytes>>>(X, out, n);
}

// round 9
// speedup vs baseline: 1.0347x; 1.0193x over previous
#include <cuda_runtime.h>
#include <math.h>

#define K 32
#define G 256
#define XMIN -6.5f
#define RANGE 13.0f
#define INV_H (G / RANGE)
#define H_STEP (RANGE / G)
#define INV_SQRT_2PI 0.3989422804014327f
#define S_CONST 0.8493218002880191f  // sqrt(0.5*log2(e))
#define EPS 2.2204460492503131e-16f
#define NCHUNK 9                     // ceil((G-1)/31)
#define NB 148
#define WPB 24

__device__ float2 g_tabF[G * K];  // (value, next-value) per (g, comp)
__device__ float2 g_tabI[G * K];

__device__ __forceinline__ float ex2f(float x) {
    float r;
    asm("ex2.approx.ftz.f32 %0, %1;" : "=f"(r) : "f"(x));
    return r;
}

// ---------------- fused prep + build (float2: value + delta) ----------------
// grid dim3(NCHUNK, 2), 512 threads. Warp w owns functions {w, w+16}; lane is a
// grid point within a 31-wide overlapping chunk (slope via shfl from lane+1).
__global__ void __launch_bounds__(512) build_kernel(const float* __restrict__ Wk0,
                                                    const float* __restrict__ W10,
                                                    const float* __restrict__ W21,
                                                    const float* __restrict__ mu,
                                                    const float* __restrict__ sigma) {
    __shared__ float4 s_tab[K * K];
    __shared__ float w0s[K];

    int lane = threadIdx.x & 31;
    int w = threadIdx.x >> 5;

    if (w == 0) {
        float v = Wk0[lane];
        float mx = v;
#pragma unroll
        for (int o = 16; o; o >>= 1) mx = fmaxf(mx, __shfl_xor_sync(~0u, mx, o));
        float e = __expf(v - mx);
        float s = e;
#pragma unroll
        for (int o = 16; o; o >>= 1) s += __shfl_xor_sync(~0u, s, o);
        w0s[lane] = e / s;
    }

    float w10v[2], w21v[2], sgv[2], muv[2];
#pragma unroll
    for (int c = 0; c < 2; c++) {
        int j = w + c * 16;
        int idx = lane * K + j;
        float v10 = W10[idx];
        float v21 = W21[idx];
        sgv[c] = sigma[idx];
        muv[c] = mu[idx];
        float mx10 = v10, mx21 = v21;
#pragma unroll
        for (int o = 16; o; o >>= 1) {
            mx10 = fmaxf(mx10, __shfl_xor_sync(~0u, mx10, o));
            mx21 = fmaxf(mx21, __shfl_xor_sync(~0u, mx21, o));
        }
        float e10 = __expf(v10 - mx10);
        float e21 = __expf(v21 - mx21);
        float s10 = e10, s21 = e21;
#pragma unroll
        for (int o = 16; o; o >>= 1) {
            s10 += __shfl_xor_sync(~0u, s10, o);
            s21 += __shfl_xor_sync(~0u, s21, o);
        }
        w10v[c] = e10 / s10;
        w21v[c] = e21 / s21;
    }
    __syncthreads();

#pragma unroll
    for (int c = 0; c < 2; c++) {
        int j = w + c * 16;
        float inv_sg = 1.f / sgv[c];
        float4 t;
        t.x = S_CONST * inv_sg;
        t.y = -S_CONST * muv[c] * inv_sg;
        t.z = w21v[c] * INV_SQRT_2PI * inv_sg;
        t.w = w10v[c] * w0s[j] * INV_SQRT_2PI * inv_sg;
        s_tab[lane * K + j] = t;
    }
    __syncthreads();

    int chunk = blockIdx.x;
    int tsel = blockIdx.y;
    int g = chunk * 31 + lane;
    if (g > G - 1) g = G - 1;
    float x = XMIN + g * H_STEP;

#pragma unroll
    for (int c = 0; c < 2; c++) {
        int f = w + c * 16;
        float v = 0.f;
        if (tsel == 0) {
#pragma unroll
            for (int j = 0; j < K; j++) {
                float4 t = s_tab[f * K + j];
                float u = fmaf(x, t.x, t.y);
                v = fmaf(t.w, ex2f(-u * u), v);
            }
        } else {
#pragma unroll
            for (int i = 0; i < K; i++) {
                float4 t = s_tab[i * K + f];
                float u = fmaf(x, t.x, t.y);
                v = fmaf(t.z, ex2f(-u * u), v);
            }
        }
        float vn = __shfl_down_sync(0xffffffffu, v, 1);
        if (lane < 31 && g < G - 1) {
            float2 e;
            e.x = v;
            e.y = vn - v;
            if (tsel == 0) g_tabF[g * K + f] = e;
            else           g_tabI[g * K + f] = e;
        }
    }
}

// ---------------- main: 148 balanced blocks, tables in 128KB smem ----------------
__global__ void __launch_bounds__(768, 1) tt_main(const float* __restrict__ X,
                                                  float* __restrict__ out,
                                                  int n, int ntasks) {
    extern __shared__ float4 dyn[];
    float4* sF = dyn;            // [G*16]: row g = 16 float4 (comps 2p,2p+1 as v,d)
    float4* sI = dyn + G * 16;

    __shared__ float4 sp[WPB][32];
    __shared__ float prodm[WPB][32][17];

    int tid = threadIdx.x;
    int lane = tid & 31;
    int w = tid >> 5;

    const float4* gF = (const float4*)g_tabF;
    const float4* gI = (const float4*)g_tabI;
#pragma unroll
    for (int i = tid; i < G * 16; i += 768) sF[i] = gF[i];
#pragma unroll
    for (int i = tid; i < G * 16; i += 768) sI[i] = gI[i];
    __syncthreads();

    int task = blockIdx.x + NB * w;   // strided: every block gets ~equal busy warps
    if (task >= ntasks) return;

    int sidx = task * 32 + lane;
    float2 x = make_float2(0.f, 0.f);
    if (sidx < n) x = ((const float2*)X)[sidx];

    float t0 = (x.x - XMIN) * INV_H;
    float t1 = (x.y - XMIN) * INV_H;
    float g0f = fminf(fmaxf(floorf(t0), 0.f), (float)(G - 2));
    float g1f = fminf(fmaxf(floorf(t1), 0.f), (float)(G - 2));
    sp[w][lane] = make_float4(g0f, t0 - g0f, g1f, t1 - g1f);
    __syncwarp();

    int half = lane >> 4;   // lanes 0-15: even sample of pair; 16-31: odd
    int pair = lane & 15;   // component pair (comps 2p, 2p+1)

#pragma unroll
    for (int t = 0; t < 16; t++) {
        float4 p = sp[w][2 * t + half];
        float4 fF = sF[((int)p.x) * 16 + pair];
        float4 fI = sI[((int)p.z) * 16 + pair];
        float vF0 = fmaf(p.y, fF.y, fF.x);
        float vF1 = fmaf(p.y, fF.w, fF.z);
        float vI0 = fmaf(p.w, fI.y, fI.x);
        float vI1 = fmaf(p.w, fI.w, fI.z);
        prodm[w][2 * t + half][pair] = vF0 * vI0 + vF1 * vI1;
    }
    __syncwarp();

    float acc = 0.f;
#pragma unroll
    for (int i = 0; i < 16; i++) acc += prodm[w][lane][i];

    if (sidx < n) out[sidx] = __logf(acc + EPS);
}

extern "C" void kernel_launch(void* const* d_in, const int* in_sizes, int n_in,
                              void* d_out, int out_size) {
    const float* X     = (const float*)d_in[0];
    const float* Wk0   = (const float*)d_in[1];
    const float* Wk1k0 = (const float*)d_in[2];
    const float* Wk2k1 = (const float*)d_in[3];
    const float* mu    = (const float*)d_in[4];
    const float* sigma = (const float*)d_in[5];
    float* out = (float*)d_out;
    int n = in_sizes[0] / 2;

    static int smem_set = 0;
    int dyn_bytes = 2 * G * K * (int)sizeof(float2);  // 131072
    if (!smem_set) {
        cudaFuncSetAttribute(tt_main, cudaFuncAttributeMaxDynamicSharedMemorySize, dyn_bytes);
        smem_set = 1;
    }

    build_kernel<<<dim3(NCHUNK, 2), 512>>>(Wk0, Wk1k0, Wk2k1, mu, sigma);
    int ntasks = (n + 31) / 32;
    tt_main<<<NB, 768, dyn_bytes>>>(X, out, n, ntasks);
}